// round 6
// baseline (speedup 1.0000x reference)
#include <cuda_runtime.h>
#include <cstdint>
#include <cstddef>

// Problem constants (fixed by the dataset)
#define KCODES   8192
#define DDIM     512
#define NROWS    32768        // B*N = 8*4096
#define BND_ELEMS 16777216ULL // B*N*D

// Scratch (no cudaMalloc allowed). Only touched from device code —
// host-passed __device__ symbol addresses resolve to the host shadow (ATS).
__device__ unsigned long long g_minpair[NROWS];
__device__ float g_cbsq[KCODES];
__device__ float g_xsq[NROWS];

// ---------------------------------------------------------------------------
// helpers
// ---------------------------------------------------------------------------
__device__ __forceinline__ unsigned int forder(float f) {
    unsigned int u = __float_as_uint(f);
    return (u & 0x80000000u) ? ~u : (u | 0x80000000u);
}

__device__ __forceinline__ unsigned long long pack_dup(float x) {
    unsigned long long r;
    asm("mov.b64 %0, {%1, %1};" : "=l"(r) : "r"(__float_as_uint(x)));
    return r;
}

__device__ __forceinline__ void unpack2(unsigned long long v, float& lo, float& hi) {
    unsigned int a, b;
    asm("mov.b64 {%0, %1}, %2;" : "=r"(a), "=r"(b) : "l"(v));
    lo = __uint_as_float(a);
    hi = __uint_as_float(b);
}

// packed f32x2 FMA: each half rounds exactly like scalar fma.rn.f32.
#define FMA_F32X2(d, a, b) \
    asm("fma.rn.f32x2 %0, %1, %2, %0;" : "+l"(d) : "l"(a), "l"(b))

__device__ __forceinline__ unsigned long long ullmin2(unsigned long long a,
                                                      unsigned long long b) {
    return a < b ? a : b;
}

// ---------------------------------------------------------------------------
// kernel 0: reset per-row argmin accumulators (re-runs on every graph replay)
// ---------------------------------------------------------------------------
__global__ void vq_init_kernel() {
    int i = blockIdx.x * blockDim.x + threadIdx.x;
    if (i < NROWS) g_minpair[i] = 0xFFFFFFFFFFFFFFFFULL;
}

// ---------------------------------------------------------------------------
// kernel 1: squared norms, STRICTLY SEQUENTIAL fp32: s = fl(s + fl(v*v)).
// ---------------------------------------------------------------------------
__device__ __forceinline__ float sqsum_row_body(const float* __restrict__ src,
                                                float tile[128][33], int tid,
                                                int r0) {
    float s = 0.0f;
    for (int c0 = 0; c0 < DDIM; c0 += 32) {
        #pragma unroll
        for (int i = tid; i < 128 * 32; i += 128) {
            int rr = i >> 5;
            int cc = i & 31;
            tile[rr][cc] = src[(size_t)(r0 + rr) * DDIM + c0 + cc];
        }
        __syncthreads();
        #pragma unroll
        for (int cc = 0; cc < 32; cc++) {
            float v = tile[tid][cc];
            s = __fadd_rn(s, __fmul_rn(v, v));
        }
        __syncthreads();
    }
    return s;
}

__global__ void __launch_bounds__(128)
vq_xsq_kernel(const float* __restrict__ src) {
    __shared__ float tile[128][33];
    int r0 = blockIdx.x * 128;
    float s = sqsum_row_body(src, tile, threadIdx.x, r0);
    g_xsq[r0 + threadIdx.x] = s;
}

__global__ void __launch_bounds__(128)
vq_cbsq_kernel(const float* __restrict__ src) {
    __shared__ float tile[128][33];
    int r0 = blockIdx.x * 128;
    float s = sqsum_row_body(src, tile, threadIdx.x, r0);
    g_cbsq[r0 + threadIdx.x] = s;
}

// ---------------------------------------------------------------------------
// kernel 2: fused fp32 GEMM (x . c) + per-row argmin of the REFERENCE score
//   score = fl( fl(cbsq[k] + xsq[row]) + fl(2*dot) ); ties -> lowest k.
//   BM=128, BN=256, BK=8; 256 threads; 8 rows x 16 cols per thread.
//   Per thread-kk: 6 LDS.128 feed 64 FFMA2 (was 4 per 32) -> the LDS/L1
//   pipe drops below the FMA pipe and fma becomes the sole bound.
//   Per-output accumulation order (d ascending, single fma.rn chain) is
//   IDENTICAL to the passing kernels -> bit-exact.
// ---------------------------------------------------------------------------
__global__ void __launch_bounds__(256, 1)
vq_gemm_argmin_kernel(const float* __restrict__ A,   // [NROWS, 512]
                      const float* __restrict__ Cb)  // [KCODES, 512]
{
    __shared__ float As[2][8][132];
    __shared__ float Bs[2][8][264];

    const int tid = threadIdx.x;
    const int tx = tid & 15;   // code sub-tile (16 cols each)
    const int ty = tid >> 4;   // row sub-tile (8 rows each)
    const int m0 = blockIdx.y * 128;
    const int k0 = blockIdx.x * 256;

    // loader assignment:
    //   A tile 128x8: row = tid>>1, cols (tid&1)*4 .. +3  (1 float4/thread)
    //   B tile 256x8: row = tid,    cols 0..7             (2 float4/thread)
    const int arow = tid >> 1;
    const int ac4  = (tid & 1) * 4;
    const float* Aptr = A  + (size_t)(m0 + arow) * DDIM + ac4;
    const float* Bptr = Cb + (size_t)(k0 + tid) * DDIM;

    unsigned long long acc[8][8];
    #pragma unroll
    for (int i = 0; i < 8; i++)
        #pragma unroll
        for (int p = 0; p < 8; p++) acc[i][p] = 0ULL;

    // prologue: fill buffer 0 (d0 = 0)
    {
        float4 va = *reinterpret_cast<const float4*>(Aptr);
        float4 b0 = *reinterpret_cast<const float4*>(Bptr);
        float4 b1 = *reinterpret_cast<const float4*>(Bptr + 4);
        As[0][ac4 + 0][arow] = va.x; As[0][ac4 + 1][arow] = va.y;
        As[0][ac4 + 2][arow] = va.z; As[0][ac4 + 3][arow] = va.w;
        Bs[0][0][tid] = b0.x; Bs[0][1][tid] = b0.y;
        Bs[0][2][tid] = b0.z; Bs[0][3][tid] = b0.w;
        Bs[0][4][tid] = b1.x; Bs[0][5][tid] = b1.y;
        Bs[0][6][tid] = b1.z; Bs[0][7][tid] = b1.w;
    }
    __syncthreads();

    int buf = 0;
    #pragma unroll 1
    for (int d0 = 8; d0 < DDIM + 8; d0 += 8) {
        const bool more = (d0 < DDIM);
        float4 na, nb0, nb1;
        if (more) {
            na  = *reinterpret_cast<const float4*>(Aptr + d0);
            nb0 = *reinterpret_cast<const float4*>(Bptr + d0);
            nb1 = *reinterpret_cast<const float4*>(Bptr + d0 + 4);
        }

        #pragma unroll
        for (int kk = 0; kk < 8; kk++) {
            float4 a0 = *reinterpret_cast<const float4*>(&As[buf][kk][ty * 8]);
            float4 a1 = *reinterpret_cast<const float4*>(&As[buf][kk][ty * 8 + 4]);
            unsigned long long ap[8];
            ap[0] = pack_dup(a0.x); ap[1] = pack_dup(a0.y);
            ap[2] = pack_dup(a0.z); ap[3] = pack_dup(a0.w);
            ap[4] = pack_dup(a1.x); ap[5] = pack_dup(a1.y);
            ap[6] = pack_dup(a1.z); ap[7] = pack_dup(a1.w);

            ulonglong2 b0 = *reinterpret_cast<const ulonglong2*>(&Bs[buf][kk][tx * 16]);
            ulonglong2 b1 = *reinterpret_cast<const ulonglong2*>(&Bs[buf][kk][tx * 16 + 4]);
            ulonglong2 b2 = *reinterpret_cast<const ulonglong2*>(&Bs[buf][kk][tx * 16 + 8]);
            ulonglong2 b3 = *reinterpret_cast<const ulonglong2*>(&Bs[buf][kk][tx * 16 + 12]);
            unsigned long long bp[8] = { b0.x, b0.y, b1.x, b1.y,
                                         b2.x, b2.y, b3.x, b3.y };

            #pragma unroll
            for (int i = 0; i < 8; i++)
                #pragma unroll
                for (int p = 0; p < 8; p++)
                    FMA_F32X2(acc[i][p], ap[i], bp[p]);
        }

        if (more) {
            int nxt = buf ^ 1;
            As[nxt][ac4 + 0][arow] = na.x; As[nxt][ac4 + 1][arow] = na.y;
            As[nxt][ac4 + 2][arow] = na.z; As[nxt][ac4 + 3][arow] = na.w;
            Bs[nxt][0][tid] = nb0.x; Bs[nxt][1][tid] = nb0.y;
            Bs[nxt][2][tid] = nb0.z; Bs[nxt][3][tid] = nb0.w;
            Bs[nxt][4][tid] = nb1.x; Bs[nxt][5][tid] = nb1.y;
            Bs[nxt][6][tid] = nb1.z; Bs[nxt][7][tid] = nb1.w;
            __syncthreads();
            buf = nxt;
        }
    }

    // epilogue: replicate reference rounding chain, per-row packed min
    #pragma unroll
    for (int i = 0; i < 8; i++) {
        const float xsq = g_xsq[m0 + ty * 8 + i];
        unsigned long long best = 0xFFFFFFFFFFFFFFFFULL;
        #pragma unroll
        for (int p = 0; p < 8; p++) {
            float lo, hi;
            unpack2(acc[i][p], lo, hi);
            int kA = k0 + tx * 16 + 2 * p;
            float tA = __fadd_rn(g_cbsq[kA],     xsq);
            float tB = __fadd_rn(g_cbsq[kA + 1], xsq);
            float sA = __fadd_rn(tA, __fmul_rn(2.0f, lo));
            float sB = __fadd_rn(tB, __fmul_rn(2.0f, hi));
            unsigned long long pA =
                ((unsigned long long)forder(sA) << 32) | (unsigned int)kA;
            unsigned long long pB =
                ((unsigned long long)forder(sB) << 32) | (unsigned int)(kA + 1);
            best = ullmin2(best, ullmin2(pA, pB));
        }
        #pragma unroll
        for (int m = 8; m; m >>= 1) {
            unsigned long long o = __shfl_xor_sync(0xFFFFFFFFu, best, m);
            best = ullmin2(best, o);
        }
        if (tx == 0) {
            atomicMin(&g_minpair[m0 + ty * 8 + i], best);
        }
    }
}

// ---------------------------------------------------------------------------
// kernel 3: gather codes (twice) + write idx as float
//   out layout: [codes BND][zqx_tilde BND][idx NROWS], all float32
// ---------------------------------------------------------------------------
__global__ void vq_gather_kernel(const float* __restrict__ cb,
                                 float* __restrict__ out) {
    int row = blockIdx.x;
    unsigned long long pair = g_minpair[row];
    unsigned int k = (unsigned int)(pair & 0xFFFFFFFFu);

    const float4* src = reinterpret_cast<const float4*>(cb + (size_t)k * DDIM);
    float4* o1 = reinterpret_cast<float4*>(out + (size_t)row * DDIM);
    float4* o2 = reinterpret_cast<float4*>(out + BND_ELEMS + (size_t)row * DDIM);
    float4 v = src[threadIdx.x];
    o1[threadIdx.x] = v;
    o2[threadIdx.x] = v;
    if (threadIdx.x == 0) {
        out[2 * BND_ELEMS + (size_t)row] = (float)k;
    }
}

// ---------------------------------------------------------------------------
// launch
// ---------------------------------------------------------------------------
extern "C" void kernel_launch(void* const* d_in, const int* in_sizes, int n_in,
                              void* d_out, int out_size) {
    (void)out_size;
    const float* z  = (const float*)d_in[0];
    const float* cb = (const float*)d_in[1];
    if (n_in >= 2 && in_sizes[0] < in_sizes[1]) {
        const float* t = z; z = cb; cb = t;
    }
    float* out = (float*)d_out;

    vq_init_kernel<<<(NROWS + 255) / 256, 256>>>();
    vq_cbsq_kernel<<<KCODES / 128, 128>>>(cb);
    vq_xsq_kernel<<<NROWS / 128, 128>>>(z);

    dim3 grid(KCODES / 256, NROWS / 128);  // (32, 256)
    vq_gemm_argmin_kernel<<<grid, 256>>>(z, cb);

    vq_gather_kernel<<<NROWS, 128>>>(cb, out);
}

// round 7
// speedup vs baseline: 1.7395x; 1.7395x over previous
#include <cuda_runtime.h>
#include <cstdint>
#include <cstddef>

// Problem constants (fixed by the dataset)
#define KCODES   8192
#define DDIM     512
#define NROWS    32768        // B*N = 8*4096
#define BND_ELEMS 16777216ULL // B*N*D

// Scratch (no cudaMalloc allowed). Only touched from device code.
__device__ unsigned long long g_minpair[NROWS];
__device__ float g_cbsq[KCODES];
__device__ float g_xsq[NROWS];

// ---------------------------------------------------------------------------
// helpers
// ---------------------------------------------------------------------------
__device__ __forceinline__ unsigned int forder(float f) {
    unsigned int u = __float_as_uint(f);
    return (u & 0x80000000u) ? ~u : (u | 0x80000000u);
}

__device__ __forceinline__ unsigned long long pack_dup(float x) {
    unsigned long long r;
    asm("mov.b64 %0, {%1, %1};" : "=l"(r) : "r"(__float_as_uint(x)));
    return r;
}

__device__ __forceinline__ void unpack2(unsigned long long v, float& lo, float& hi) {
    unsigned int a, b;
    asm("mov.b64 {%0, %1}, %2;" : "=r"(a), "=r"(b) : "l"(v));
    lo = __uint_as_float(a);
    hi = __uint_as_float(b);
}

// packed f32x2 FMA: each half rounds exactly like scalar fma.rn.f32.
#define FMA_F32X2(d, a, b) \
    asm("fma.rn.f32x2 %0, %1, %2, %0;" : "+l"(d) : "l"(a), "l"(b))

__device__ __forceinline__ unsigned long long ullmin2(unsigned long long a,
                                                      unsigned long long b) {
    return a < b ? a : b;
}

// ---------------------------------------------------------------------------
// kernel 0: reset per-row argmin accumulators (re-runs on every graph replay)
// ---------------------------------------------------------------------------
__global__ void vq_init_kernel() {
    int i = blockIdx.x * blockDim.x + threadIdx.x;
    if (i < NROWS) g_minpair[i] = 0xFFFFFFFFFFFFFFFFULL;
}

// ---------------------------------------------------------------------------
// kernel 1: squared norms, STRICTLY SEQUENTIAL fp32: s = fl(s + fl(v*v)).
// ---------------------------------------------------------------------------
__device__ __forceinline__ float sqsum_row_body(const float* __restrict__ src,
                                                float tile[128][33], int tid,
                                                int r0) {
    float s = 0.0f;
    for (int c0 = 0; c0 < DDIM; c0 += 32) {
        #pragma unroll
        for (int i = tid; i < 128 * 32; i += 128) {
            int rr = i >> 5;
            int cc = i & 31;
            tile[rr][cc] = src[(size_t)(r0 + rr) * DDIM + c0 + cc];
        }
        __syncthreads();
        #pragma unroll
        for (int cc = 0; cc < 32; cc++) {
            float v = tile[tid][cc];
            s = __fadd_rn(s, __fmul_rn(v, v));
        }
        __syncthreads();
    }
    return s;
}

__global__ void __launch_bounds__(128)
vq_xsq_kernel(const float* __restrict__ src) {
    __shared__ float tile[128][33];
    int r0 = blockIdx.x * 128;
    float s = sqsum_row_body(src, tile, threadIdx.x, r0);
    g_xsq[r0 + threadIdx.x] = s;
}

__global__ void __launch_bounds__(128)
vq_cbsq_kernel(const float* __restrict__ src) {
    __shared__ float tile[128][33];
    int r0 = blockIdx.x * 128;
    float s = sqsum_row_body(src, tile, threadIdx.x, r0);
    g_cbsq[r0 + threadIdx.x] = s;
}

// ---------------------------------------------------------------------------
// kernel 2: fused fp32 GEMM (x . c) + per-row argmin of the REFERENCE score
//   score = fl( fl(cbsq[k] + xsq[row]) + fl(2*dot) ); ties -> lowest k.
//   BM=128, BN=256, BK=16; 256 threads; 8 rows x 16 cols per thread.
//   Thread tx owns B columns {g*64 + tx*4 + 0..3}, g=0..3: each B LDS.128
//   has a 16B lane stride -> one contiguous 128B wavefront per phase ->
//   ZERO bank conflicts (the R6 tx*16 layout had 4-way conflicts).
//   Per-output accumulation order (d ascending, single fma.rn chain) is
//   IDENTICAL to the passing kernels -> bit-exact.
// ---------------------------------------------------------------------------
__global__ void __launch_bounds__(256, 1)
vq_gemm_argmin_kernel(const float* __restrict__ A,   // [NROWS, 512]
                      const float* __restrict__ Cb)  // [KCODES, 512]
{
    __shared__ float As[2][16][132];
    __shared__ float Bs[2][16][264];

    const int tid = threadIdx.x;
    const int tx = tid & 15;   // code sub-tile
    const int ty = tid >> 4;   // row sub-tile (8 rows each)
    const int m0 = blockIdx.y * 128;
    const int k0 = blockIdx.x * 256;

    // loader assignment (BK=16 stage):
    //   A tile 128x16: row = tid>>1, cols (tid&1)*4 + {0..3, 8..11}
    //   B tile 256x16: row = tid,    cols 0..15  (4 float4)
    const int arow = tid >> 1;
    const int ac4  = (tid & 1) * 4;
    const float* Aptr = A  + (size_t)(m0 + arow) * DDIM + ac4;
    const float* Bptr = Cb + (size_t)(k0 + tid) * DDIM;

    unsigned long long acc[8][8];
    #pragma unroll
    for (int i = 0; i < 8; i++)
        #pragma unroll
        for (int p = 0; p < 8; p++) acc[i][p] = 0ULL;

    // prologue: fill buffer 0 (d0 = 0)
    {
        float4 a0 = *reinterpret_cast<const float4*>(Aptr);
        float4 a1 = *reinterpret_cast<const float4*>(Aptr + 8);
        As[0][ac4 + 0][arow] = a0.x; As[0][ac4 + 1][arow] = a0.y;
        As[0][ac4 + 2][arow] = a0.z; As[0][ac4 + 3][arow] = a0.w;
        As[0][ac4 + 8][arow] = a1.x; As[0][ac4 + 9][arow] = a1.y;
        As[0][ac4 + 10][arow] = a1.z; As[0][ac4 + 11][arow] = a1.w;
        #pragma unroll
        for (int g = 0; g < 4; g++) {
            float4 b = *reinterpret_cast<const float4*>(Bptr + g * 4);
            Bs[0][g * 4 + 0][tid] = b.x; Bs[0][g * 4 + 1][tid] = b.y;
            Bs[0][g * 4 + 2][tid] = b.z; Bs[0][g * 4 + 3][tid] = b.w;
        }
    }
    __syncthreads();

    int buf = 0;
    #pragma unroll 1
    for (int d0 = 16; d0 < DDIM + 16; d0 += 16) {
        const bool more = (d0 < DDIM);
        float4 na0, na1, nb[4];
        if (more) {
            na0 = *reinterpret_cast<const float4*>(Aptr + d0);
            na1 = *reinterpret_cast<const float4*>(Aptr + d0 + 8);
            #pragma unroll
            for (int g = 0; g < 4; g++)
                nb[g] = *reinterpret_cast<const float4*>(Bptr + d0 + g * 4);
        }

        #pragma unroll
        for (int kk = 0; kk < 16; kk++) {
            float4 a0 = *reinterpret_cast<const float4*>(&As[buf][kk][ty * 8]);
            float4 a1 = *reinterpret_cast<const float4*>(&As[buf][kk][ty * 8 + 4]);
            unsigned long long ap[8];
            ap[0] = pack_dup(a0.x); ap[1] = pack_dup(a0.y);
            ap[2] = pack_dup(a0.z); ap[3] = pack_dup(a0.w);
            ap[4] = pack_dup(a1.x); ap[5] = pack_dup(a1.y);
            ap[6] = pack_dup(a1.z); ap[7] = pack_dup(a1.w);

            // conflict-free B reads: 16B lane stride within each group
            ulonglong2 b0 = *reinterpret_cast<const ulonglong2*>(&Bs[buf][kk][tx * 4]);
            ulonglong2 b1 = *reinterpret_cast<const ulonglong2*>(&Bs[buf][kk][64 + tx * 4]);
            ulonglong2 b2 = *reinterpret_cast<const ulonglong2*>(&Bs[buf][kk][128 + tx * 4]);
            ulonglong2 b3 = *reinterpret_cast<const ulonglong2*>(&Bs[buf][kk][192 + tx * 4]);
            unsigned long long bp[8] = { b0.x, b0.y, b1.x, b1.y,
                                         b2.x, b2.y, b3.x, b3.y };

            #pragma unroll
            for (int i = 0; i < 8; i++)
                #pragma unroll
                for (int p = 0; p < 8; p++)
                    FMA_F32X2(acc[i][p], ap[i], bp[p]);
        }

        if (more) {
            int nxt = buf ^ 1;
            As[nxt][ac4 + 0][arow] = na0.x; As[nxt][ac4 + 1][arow] = na0.y;
            As[nxt][ac4 + 2][arow] = na0.z; As[nxt][ac4 + 3][arow] = na0.w;
            As[nxt][ac4 + 8][arow] = na1.x; As[nxt][ac4 + 9][arow] = na1.y;
            As[nxt][ac4 + 10][arow] = na1.z; As[nxt][ac4 + 11][arow] = na1.w;
            #pragma unroll
            for (int g = 0; g < 4; g++) {
                Bs[nxt][g * 4 + 0][tid] = nb[g].x;
                Bs[nxt][g * 4 + 1][tid] = nb[g].y;
                Bs[nxt][g * 4 + 2][tid] = nb[g].z;
                Bs[nxt][g * 4 + 3][tid] = nb[g].w;
            }
            __syncthreads();
            buf = nxt;
        }
    }

    // epilogue: replicate reference rounding chain, per-row packed min.
    // acc[i][p] covers cols kA = k0 + (p>>1)*64 + tx*4 + (p&1)*2 + {0,1}
    #pragma unroll
    for (int i = 0; i < 8; i++) {
        const float xsq = g_xsq[m0 + ty * 8 + i];
        unsigned long long best = 0xFFFFFFFFFFFFFFFFULL;
        #pragma unroll
        for (int p = 0; p < 8; p++) {
            float lo, hi;
            unpack2(acc[i][p], lo, hi);
            int kA = k0 + (p >> 1) * 64 + tx * 4 + (p & 1) * 2;
            float tA = __fadd_rn(g_cbsq[kA],     xsq);
            float tB = __fadd_rn(g_cbsq[kA + 1], xsq);
            float sA = __fadd_rn(tA, __fmul_rn(2.0f, lo));
            float sB = __fadd_rn(tB, __fmul_rn(2.0f, hi));
            unsigned long long pA =
                ((unsigned long long)forder(sA) << 32) | (unsigned int)kA;
            unsigned long long pB =
                ((unsigned long long)forder(sB) << 32) | (unsigned int)(kA + 1);
            best = ullmin2(best, ullmin2(pA, pB));
        }
        #pragma unroll
        for (int m = 8; m; m >>= 1) {
            unsigned long long o = __shfl_xor_sync(0xFFFFFFFFu, best, m);
            best = ullmin2(best, o);
        }
        if (tx == 0) {
            atomicMin(&g_minpair[m0 + ty * 8 + i], best);
        }
    }
}

// ---------------------------------------------------------------------------
// kernel 3: gather codes (twice) + write idx as float
//   out layout: [codes BND][zqx_tilde BND][idx NROWS], all float32
// ---------------------------------------------------------------------------
__global__ void vq_gather_kernel(const float* __restrict__ cb,
                                 float* __restrict__ out) {
    int row = blockIdx.x;
    unsigned long long pair = g_minpair[row];
    unsigned int k = (unsigned int)(pair & 0xFFFFFFFFu);

    const float4* src = reinterpret_cast<const float4*>(cb + (size_t)k * DDIM);
    float4* o1 = reinterpret_cast<float4*>(out + (size_t)row * DDIM);
    float4* o2 = reinterpret_cast<float4*>(out + BND_ELEMS + (size_t)row * DDIM);
    float4 v = src[threadIdx.x];
    o1[threadIdx.x] = v;
    o2[threadIdx.x] = v;
    if (threadIdx.x == 0) {
        out[2 * BND_ELEMS + (size_t)row] = (float)k;
    }
}

// ---------------------------------------------------------------------------
// launch
// ---------------------------------------------------------------------------
extern "C" void kernel_launch(void* const* d_in, const int* in_sizes, int n_in,
                              void* d_out, int out_size) {
    (void)out_size;
    const float* z  = (const float*)d_in[0];
    const float* cb = (const float*)d_in[1];
    if (n_in >= 2 && in_sizes[0] < in_sizes[1]) {
        const float* t = z; z = cb; cb = t;
    }
    float* out = (float*)d_out;

    vq_init_kernel<<<(NROWS + 255) / 256, 256>>>();
    vq_cbsq_kernel<<<KCODES / 128, 128>>>(cb);
    vq_xsq_kernel<<<NROWS / 128, 128>>>(z);

    dim3 grid(KCODES / 256, NROWS / 128);  // (32, 256)
    vq_gemm_argmin_kernel<<<grid, 256>>>(z, cb);

    vq_gather_kernel<<<NROWS, 128>>>(cb, out);
}

// round 8
// speedup vs baseline: 2.0147x; 1.1582x over previous
#include <cuda_runtime.h>
#include <cstdint>
#include <cstddef>

// Problem constants (fixed by the dataset)
#define KCODES   8192
#define DDIM     512
#define NROWS    32768        // B*N = 8*4096
#define BND_ELEMS 16777216ULL // B*N*D

// Scratch (no cudaMalloc allowed). Only touched from device code.
__device__ unsigned long long g_minpair[NROWS];
__device__ float g_cbsq[KCODES];
__device__ float g_xsq[NROWS];

// ---------------------------------------------------------------------------
// helpers
// ---------------------------------------------------------------------------
__device__ __forceinline__ unsigned int forder(float f) {
    unsigned int u = __float_as_uint(f);
    return (u & 0x80000000u) ? ~u : (u | 0x80000000u);
}

__device__ __forceinline__ unsigned long long pack_dup(float x) {
    unsigned long long r;
    asm("mov.b64 %0, {%1, %1};" : "=l"(r) : "r"(__float_as_uint(x)));
    return r;
}

__device__ __forceinline__ void unpack2(unsigned long long v, float& lo, float& hi) {
    unsigned int a, b;
    asm("mov.b64 {%0, %1}, %2;" : "=r"(a), "=r"(b) : "l"(v));
    lo = __uint_as_float(a);
    hi = __uint_as_float(b);
}

// packed f32x2 FMA: each half rounds exactly like scalar fma.rn.f32.
#define FMA_F32X2(d, a, b) \
    asm("fma.rn.f32x2 %0, %1, %2, %0;" : "+l"(d) : "l"(a), "l"(b))

__device__ __forceinline__ unsigned long long ullmin2(unsigned long long a,
                                                      unsigned long long b) {
    return a < b ? a : b;
}

// ---------------------------------------------------------------------------
// kernel 0: reset per-row argmin accumulators (re-runs on every graph replay)
// ---------------------------------------------------------------------------
__global__ void vq_init_kernel() {
    int i = blockIdx.x * blockDim.x + threadIdx.x;
    if (i < NROWS) g_minpair[i] = 0xFFFFFFFFFFFFFFFFULL;
}

// ---------------------------------------------------------------------------
// kernel 1: squared norms, STRICTLY SEQUENTIAL fp32: s = fl(s + fl(v*v)).
// ---------------------------------------------------------------------------
__device__ __forceinline__ float sqsum_row_body(const float* __restrict__ src,
                                                float tile[128][33], int tid,
                                                int r0) {
    float s = 0.0f;
    for (int c0 = 0; c0 < DDIM; c0 += 32) {
        #pragma unroll
        for (int i = tid; i < 128 * 32; i += 128) {
            int rr = i >> 5;
            int cc = i & 31;
            tile[rr][cc] = src[(size_t)(r0 + rr) * DDIM + c0 + cc];
        }
        __syncthreads();
        #pragma unroll
        for (int cc = 0; cc < 32; cc++) {
            float v = tile[tid][cc];
            s = __fadd_rn(s, __fmul_rn(v, v));
        }
        __syncthreads();
    }
    return s;
}

__global__ void __launch_bounds__(128)
vq_xsq_kernel(const float* __restrict__ src) {
    __shared__ float tile[128][33];
    int r0 = blockIdx.x * 128;
    float s = sqsum_row_body(src, tile, threadIdx.x, r0);
    g_xsq[r0 + threadIdx.x] = s;
}

__global__ void __launch_bounds__(128)
vq_cbsq_kernel(const float* __restrict__ src) {
    __shared__ float tile[128][33];
    int r0 = blockIdx.x * 128;
    float s = sqsum_row_body(src, tile, threadIdx.x, r0);
    g_cbsq[r0 + threadIdx.x] = s;
}

// ---------------------------------------------------------------------------
// kernel 2: fused fp32 GEMM (x . c) + per-row argmin of the REFERENCE score
//   score = fl( fl(cbsq[k] + xsq[row]) + fl(2*dot) ); ties -> lowest k.
//   BM=128, BN=128, BK=16; 256 threads; 8 rows x 8 cols per thread;
//   TWO CTAs per SM (16 warps) for latency coverage. Thread tx owns B cols
//   {g*64 + tx*4 + 0..3}, g=0..1 -> 16B lane stride, zero bank conflicts.
//   Per-output accumulation order (d ascending, single fma.rn chain) is
//   IDENTICAL to the passing kernels -> bit-exact.
// ---------------------------------------------------------------------------
__global__ void __launch_bounds__(256, 2)
vq_gemm_argmin_kernel(const float* __restrict__ A,   // [NROWS, 512]
                      const float* __restrict__ Cb)  // [KCODES, 512]
{
    __shared__ float As[2][16][132];
    __shared__ float Bs[2][16][132];

    const int tid = threadIdx.x;
    const int tx = tid & 15;   // code sub-tile
    const int ty = tid >> 4;   // row sub-tile (8 rows each)
    const int m0 = blockIdx.y * 128;
    const int k0 = blockIdx.x * 128;

    // loader assignment (BK=16 stage; both tiles are 128 rows x 16 cols):
    //   row = tid>>1, cols (tid&1)*8 .. +7 (2 float4 per matrix per thread)
    const int lrow = tid >> 1;
    const int lc8  = (tid & 1) * 8;
    const float* Aptr = A  + (size_t)(m0 + lrow) * DDIM + lc8;
    const float* Bptr = Cb + (size_t)(k0 + lrow) * DDIM + lc8;

    unsigned long long acc[8][4];
    #pragma unroll
    for (int i = 0; i < 8; i++)
        #pragma unroll
        for (int p = 0; p < 4; p++) acc[i][p] = 0ULL;

    // prologue: fill buffer 0 (d0 = 0)
    {
        float4 a0 = *reinterpret_cast<const float4*>(Aptr);
        float4 a1 = *reinterpret_cast<const float4*>(Aptr + 4);
        float4 b0 = *reinterpret_cast<const float4*>(Bptr);
        float4 b1 = *reinterpret_cast<const float4*>(Bptr + 4);
        As[0][lc8 + 0][lrow] = a0.x; As[0][lc8 + 1][lrow] = a0.y;
        As[0][lc8 + 2][lrow] = a0.z; As[0][lc8 + 3][lrow] = a0.w;
        As[0][lc8 + 4][lrow] = a1.x; As[0][lc8 + 5][lrow] = a1.y;
        As[0][lc8 + 6][lrow] = a1.z; As[0][lc8 + 7][lrow] = a1.w;
        Bs[0][lc8 + 0][lrow] = b0.x; Bs[0][lc8 + 1][lrow] = b0.y;
        Bs[0][lc8 + 2][lrow] = b0.z; Bs[0][lc8 + 3][lrow] = b0.w;
        Bs[0][lc8 + 4][lrow] = b1.x; Bs[0][lc8 + 5][lrow] = b1.y;
        Bs[0][lc8 + 6][lrow] = b1.z; Bs[0][lc8 + 7][lrow] = b1.w;
    }
    __syncthreads();

    int buf = 0;
    #pragma unroll 1
    for (int d0 = 16; d0 < DDIM + 16; d0 += 16) {
        const bool more = (d0 < DDIM);
        float4 na0, na1, nb0, nb1;
        if (more) {
            na0 = *reinterpret_cast<const float4*>(Aptr + d0);
            na1 = *reinterpret_cast<const float4*>(Aptr + d0 + 4);
            nb0 = *reinterpret_cast<const float4*>(Bptr + d0);
            nb1 = *reinterpret_cast<const float4*>(Bptr + d0 + 4);
        }

        #pragma unroll
        for (int kk = 0; kk < 16; kk++) {
            float4 a0 = *reinterpret_cast<const float4*>(&As[buf][kk][ty * 8]);
            float4 a1 = *reinterpret_cast<const float4*>(&As[buf][kk][ty * 8 + 4]);
            unsigned long long ap[8];
            ap[0] = pack_dup(a0.x); ap[1] = pack_dup(a0.y);
            ap[2] = pack_dup(a0.z); ap[3] = pack_dup(a0.w);
            ap[4] = pack_dup(a1.x); ap[5] = pack_dup(a1.y);
            ap[6] = pack_dup(a1.z); ap[7] = pack_dup(a1.w);

            // conflict-free B reads: 16B lane stride within each 64-col group
            ulonglong2 b0 = *reinterpret_cast<const ulonglong2*>(&Bs[buf][kk][tx * 4]);
            ulonglong2 b1 = *reinterpret_cast<const ulonglong2*>(&Bs[buf][kk][64 + tx * 4]);
            unsigned long long bp[4] = { b0.x, b0.y, b1.x, b1.y };

            #pragma unroll
            for (int i = 0; i < 8; i++)
                #pragma unroll
                for (int p = 0; p < 4; p++)
                    FMA_F32X2(acc[i][p], ap[i], bp[p]);
        }

        if (more) {
            int nxt = buf ^ 1;
            As[nxt][lc8 + 0][lrow] = na0.x; As[nxt][lc8 + 1][lrow] = na0.y;
            As[nxt][lc8 + 2][lrow] = na0.z; As[nxt][lc8 + 3][lrow] = na0.w;
            As[nxt][lc8 + 4][lrow] = na1.x; As[nxt][lc8 + 5][lrow] = na1.y;
            As[nxt][lc8 + 6][lrow] = na1.z; As[nxt][lc8 + 7][lrow] = na1.w;
            Bs[nxt][lc8 + 0][lrow] = nb0.x; Bs[nxt][lc8 + 1][lrow] = nb0.y;
            Bs[nxt][lc8 + 2][lrow] = nb0.z; Bs[nxt][lc8 + 3][lrow] = nb0.w;
            Bs[nxt][lc8 + 4][lrow] = nb1.x; Bs[nxt][lc8 + 5][lrow] = nb1.y;
            Bs[nxt][lc8 + 6][lrow] = nb1.z; Bs[nxt][lc8 + 7][lrow] = nb1.w;
            __syncthreads();
            buf = nxt;
        }
    }

    // epilogue: replicate reference rounding chain, per-row packed min.
    // acc[i][p] covers cols kA = k0 + (p>>1)*64 + tx*4 + (p&1)*2 + {0,1}
    #pragma unroll
    for (int i = 0; i < 8; i++) {
        const float xsq = g_xsq[m0 + ty * 8 + i];
        unsigned long long best = 0xFFFFFFFFFFFFFFFFULL;
        #pragma unroll
        for (int p = 0; p < 4; p++) {
            float lo, hi;
            unpack2(acc[i][p], lo, hi);
            int kA = k0 + (p >> 1) * 64 + tx * 4 + (p & 1) * 2;
            float tA = __fadd_rn(g_cbsq[kA],     xsq);
            float tB = __fadd_rn(g_cbsq[kA + 1], xsq);
            float sA = __fadd_rn(tA, __fmul_rn(2.0f, lo));
            float sB = __fadd_rn(tB, __fmul_rn(2.0f, hi));
            unsigned long long pA =
                ((unsigned long long)forder(sA) << 32) | (unsigned int)kA;
            unsigned long long pB =
                ((unsigned long long)forder(sB) << 32) | (unsigned int)(kA + 1);
            best = ullmin2(best, ullmin2(pA, pB));
        }
        #pragma unroll
        for (int m = 8; m; m >>= 1) {
            unsigned long long o = __shfl_xor_sync(0xFFFFFFFFu, best, m);
            best = ullmin2(best, o);
        }
        if (tx == 0) {
            atomicMin(&g_minpair[m0 + ty * 8 + i], best);
        }
    }
}

// ---------------------------------------------------------------------------
// kernel 3: gather codes (twice) + write idx as float
//   out layout: [codes BND][zqx_tilde BND][idx NROWS], all float32
// ---------------------------------------------------------------------------
__global__ void vq_gather_kernel(const float* __restrict__ cb,
                                 float* __restrict__ out) {
    int row = blockIdx.x;
    unsigned long long pair = g_minpair[row];
    unsigned int k = (unsigned int)(pair & 0xFFFFFFFFu);

    const float4* src = reinterpret_cast<const float4*>(cb + (size_t)k * DDIM);
    float4* o1 = reinterpret_cast<float4*>(out + (size_t)row * DDIM);
    float4* o2 = reinterpret_cast<float4*>(out + BND_ELEMS + (size_t)row * DDIM);
    float4 v = src[threadIdx.x];
    o1[threadIdx.x] = v;
    o2[threadIdx.x] = v;
    if (threadIdx.x == 0) {
        out[2 * BND_ELEMS + (size_t)row] = (float)k;
    }
}

// ---------------------------------------------------------------------------
// launch
// ---------------------------------------------------------------------------
extern "C" void kernel_launch(void* const* d_in, const int* in_sizes, int n_in,
                              void* d_out, int out_size) {
    (void)out_size;
    const float* z  = (const float*)d_in[0];
    const float* cb = (const float*)d_in[1];
    if (n_in >= 2 && in_sizes[0] < in_sizes[1]) {
        const float* t = z; z = cb; cb = t;
    }
    float* out = (float*)d_out;

    vq_init_kernel<<<(NROWS + 255) / 256, 256>>>();
    vq_cbsq_kernel<<<KCODES / 128, 128>>>(cb);
    vq_xsq_kernel<<<NROWS / 128, 128>>>(z);

    dim3 grid(KCODES / 128, NROWS / 128);  // (64, 256)
    vq_gemm_argmin_kernel<<<grid, 256>>>(z, cb);

    vq_gather_kernel<<<NROWS, 128>>>(cb, out);
}